// round 16
// baseline (speedup 1.0000x reference)
#include <cuda_runtime.h>
#include <cuda_fp16.h>
#include <math.h>
#include <stdint.h>

#define BB 2
#define LL 2048
#define DD 1024
#define HH 16
#define HDIM 64
#define HIDD 4096
#define NROWS (BB*LL)   // 4096
#define QS 3072         // packed qkv row stride

// ---------------- scratch (static device globals; no allocation) ----------------
__device__ __half g_ln1_h [NROWS*DD];
__device__ __half g_qkv_h [(size_t)NROWS*QS];
__device__ __half g_attn_h[NROWS*DD];
__device__ float  g_h     [NROWS*DD];
__device__ __half g_ln2_h [NROWS*DD];
__device__ __half g_f_h   [(size_t)NROWS*HIDD];
__device__ __half g_wh    [16*1024*1024];   // packed fp16 weights

// ---------------- PTX helpers ----------------
__device__ __forceinline__ void cp16(uint32_t saddr, const void* gaddr) {
    asm volatile("cp.async.cg.shared.global [%0], [%1], 16;" :: "r"(saddr), "l"(gaddr));
}
__device__ __forceinline__ uint32_t f16x2(float lo, float hi) {
    uint32_t r;
    asm("cvt.rn.f16x2.f32 %0, %1, %2;" : "=r"(r) : "f"(hi), "f"(lo));
    return r;
}
__device__ __forceinline__ void mma_f16(float c[4],
                                        const uint32_t a[4], const uint32_t b[2]) {
    asm volatile(
        "mma.sync.aligned.m16n8k16.row.col.f32.f16.f16.f32 "
        "{%0,%1,%2,%3}, {%4,%5,%6,%7}, {%8,%9}, {%0,%1,%2,%3};"
        : "+f"(c[0]), "+f"(c[1]), "+f"(c[2]), "+f"(c[3])
        : "r"(a[0]), "r"(a[1]), "r"(a[2]), "r"(a[3]), "r"(b[0]), "r"(b[1]));
}
__device__ __forceinline__ void ldsm4(uint32_t& r0, uint32_t& r1,
                                      uint32_t& r2, uint32_t& r3, uint32_t addr) {
    asm volatile("ldmatrix.sync.aligned.m8n8.x4.shared.b16 {%0,%1,%2,%3}, [%4];"
                 : "=r"(r0), "=r"(r1), "=r"(r2), "=r"(r3) : "r"(addr));
}
__device__ __forceinline__ void ldsm4t(uint32_t& r0, uint32_t& r1,
                                       uint32_t& r2, uint32_t& r3, uint32_t addr) {
    asm volatile("ldmatrix.sync.aligned.m8n8.x4.trans.shared.b16 {%0,%1,%2,%3}, [%4];"
                 : "=r"(r0), "=r"(r1), "=r"(r2), "=r"(r3) : "r"(addr));
}

// ---------------- weight prep ----------------
__global__ __launch_bounds__(256) void cvt_w3(const float* __restrict__ a,
                                              const float* __restrict__ b,
                                              const float* __restrict__ c,
                                              __half* __restrict__ outp, int n4)
{
    const int i = blockIdx.x * 256 + threadIdx.x;
    if (i < 3 * n4) {
        const int sel = i / n4;
        const int j   = i - sel * n4;
        const float* src = (sel == 0) ? a : (sel == 1) ? b : c;
        const float4 v = reinterpret_cast<const float4*>(src)[j];
        uint2 o;
        o.x = f16x2(v.x, v.y);
        o.y = f16x2(v.z, v.w);
        reinterpret_cast<uint2*>(outp)[i] = o;
    }
}
__global__ __launch_bounds__(256) void cvt_w(const float* __restrict__ in,
                                             __half* __restrict__ outp, int n4)
{
    const int i = blockIdx.x * 256 + threadIdx.x;
    if (i < n4) {
        const float4 v = reinterpret_cast<const float4*>(in)[i];
        uint2 o;
        o.x = f16x2(v.x, v.y);
        o.y = f16x2(v.z, v.w);
        reinterpret_cast<uint2*>(outp)[i] = o;
    }
}
__global__ __launch_bounds__(256) void cvt_ilv(const float* __restrict__ w1,
                                               const float* __restrict__ wg,
                                               __half* __restrict__ outp)
{
    const int t = blockIdx.x * 256 + threadIdx.x;
    if (t < HIDD * (DD/4)) {
        const int j  = t / (DD/4);
        const int k4 = t % (DD/4);
        const float4 a = reinterpret_cast<const float4*>(w1)[t];
        const float4 g = reinterpret_cast<const float4*>(wg)[t];
        uint2 oa, og;
        oa.x = f16x2(a.x, a.y); oa.y = f16x2(a.z, a.w);
        og.x = f16x2(g.x, g.y); og.y = f16x2(g.z, g.w);
        reinterpret_cast<uint2*>(outp)[(size_t)(2*j)     * (DD/4) + k4] = oa;
        reinterpret_cast<uint2*>(outp)[(size_t)(2*j + 1) * (DD/4) + k4] = og;
    }
}

// ---------------- LayerNorm (fp16-RN output) ----------------
__global__ __launch_bounds__(256) void ln_kernel(const float* __restrict__ x,
                                                 const float* __restrict__ gamma,
                                                 const float* __restrict__ beta,
                                                 __half* __restrict__ y)
{
    const int row = blockIdx.x;
    const int tid = threadIdx.x;
    const float4 v = reinterpret_cast<const float4*>(x + (size_t)row * DD)[tid];
    float s = v.x + v.y + v.z + v.w;
    float q = v.x*v.x + v.y*v.y + v.z*v.z + v.w*v.w;
    #pragma unroll
    for (int o = 16; o >= 1; o >>= 1) {
        s += __shfl_xor_sync(0xffffffffu, s, o);
        q += __shfl_xor_sync(0xffffffffu, q, o);
    }
    __shared__ float ss[8], sq[8];
    __shared__ float stats[2];
    const int wid = tid >> 5;
    if ((tid & 31) == 0) { ss[wid] = s; sq[wid] = q; }
    __syncthreads();
    if (tid == 0) {
        float ts = 0.f, tq = 0.f;
        #pragma unroll
        for (int i = 0; i < 8; i++) { ts += ss[i]; tq += sq[i]; }
        float mu  = ts * (1.0f / DD);
        float var = tq * (1.0f / DD) - mu * mu;
        stats[0] = mu;
        stats[1] = rsqrtf(var + 1e-5f);
    }
    __syncthreads();
    const float mu = stats[0], rs = stats[1];
    const float4 g4 = reinterpret_cast<const float4*>(gamma)[tid];
    const float4 b4 = reinterpret_cast<const float4*>(beta)[tid];
    uint2 o;
    o.x = f16x2((v.x - mu) * rs * g4.x + b4.x, (v.y - mu) * rs * g4.y + b4.y);
    o.y = f16x2((v.z - mu) * rs * g4.z + b4.z, (v.w - mu) * rs * g4.w + b4.w);
    reinterpret_cast<uint2*>(y + (size_t)row * DD)[tid] = o;
}

// ---------------- FP16 mma.sync GEMM (NT): 8 warps, 64x32 tiles (frozen) ----------------
#define EP_F16       0
#define EP_RES       1
#define EP_SILU_PAIR 2
#define EP_BIAS_RES  3

#define GBK   64
#define GROWB 144
#define STG_BYTES (128 * GROWB)
#define N_STG 3
#define GEMM_SMEM_BYTES (N_STG * 2 * STG_BYTES)   // 110592

__global__ __launch_bounds__(256, 2) void mma_gemm_f16(
    const __half* __restrict__ A, const __half* __restrict__ W,
    void* __restrict__ Cv, int M, int N, int K,
    const float* __restrict__ bias, const float* __restrict__ res, int mode)
{
    extern __shared__ char smc[];
    const uint32_t sBase = (uint32_t)__cvta_generic_to_shared(smc);
    const uint32_t sAbase = sBase;
    const uint32_t sBbase = sBase + N_STG * STG_BYTES;

    const int tid  = threadIdx.x;
    const int lane = tid & 31;
    const int warp = tid >> 5;
    const int g    = lane >> 2;
    const int t4   = lane & 3;
    const int wm   = (warp >> 2) * 64;
    const int wn   = (warp & 3)  * 32;
    const int row0 = blockIdx.y * 128;
    const int col0 = blockIdx.x * 128;

    const int lr  = tid >> 3;
    const int lc  = (tid & 7) * 8;

    const __half* Ag = A + (size_t)(row0 + lr) * K + lc;
    const __half* Wg = W + (size_t)(col0 + lr) * K + lc;
    const uint32_t sA = sAbase + (uint32_t)(lr * GROWB + (tid & 7) * 16);
    const uint32_t sB = sBbase + (uint32_t)(lr * GROWB + (tid & 7) * 16);
    const uint32_t rowB = (uint32_t)(32 * GROWB);

    const int mi = lane >> 3;
    const int ri = lane & 7;
    uint32_t aAddr[4], bAddr[2];
    #pragma unroll
    for (int mt = 0; mt < 4; mt++)
        aAddr[mt] = sAbase + (uint32_t)((wm + mt * 16 + (mi & 1) * 8 + ri) * GROWB
                                        + (mi >> 1) * 16);
    #pragma unroll
    for (int p = 0; p < 2; p++)
        bAddr[p] = sBbase + (uint32_t)((wn + (2 * p + (mi >> 1)) * 8 + ri) * GROWB
                                       + (mi & 1) * 16);

    float acc[4][4][4];
    #pragma unroll
    for (int mt = 0; mt < 4; mt++)
        #pragma unroll
        for (int nt = 0; nt < 4; nt++)
            #pragma unroll
            for (int i = 0; i < 4; i++) acc[mt][nt][i] = 0.f;

    const int nk = K / GBK;

    #pragma unroll
    for (int st = 0; st < 2; st++) {
        const int ko = st * GBK;
        const uint32_t so = (uint32_t)st * STG_BYTES;
        #pragma unroll
        for (int i = 0; i < 4; i++) {
            cp16(sA + so + (uint32_t)i * rowB, Ag + (size_t)(i * 32) * K + ko);
            cp16(sB + so + (uint32_t)i * rowB, Wg + (size_t)(i * 32) * K + ko);
        }
        asm volatile("cp.async.commit_group;");
    }

    int sc = 0;
    for (int kt = 0; kt < nk; kt++) {
        asm volatile("cp.async.wait_group 1;");
        __syncthreads();

        if (kt + 2 < nk) {
            const int ko = (kt + 2) * GBK;
            int sl = sc + 2; if (sl >= N_STG) sl -= N_STG;
            const uint32_t so = (uint32_t)sl * STG_BYTES;
            #pragma unroll
            for (int i = 0; i < 4; i++) {
                cp16(sA + so + (uint32_t)i * rowB, Ag + (size_t)(i * 32) * K + ko);
                cp16(sB + so + (uint32_t)i * rowB, Wg + (size_t)(i * 32) * K + ko);
            }
        }
        asm volatile("cp.async.commit_group;");

        const uint32_t stOff = (uint32_t)sc * STG_BYTES;
        #pragma unroll
        for (int ks = 0; ks < 4; ks++) {
            const uint32_t kOff = stOff + (uint32_t)(ks * 32);
            uint32_t af[4][4];
            uint32_t bf[4][2];
            #pragma unroll
            for (int mt = 0; mt < 4; mt++)
                ldsm4(af[mt][0], af[mt][1], af[mt][2], af[mt][3], aAddr[mt] + kOff);
            #pragma unroll
            for (int p = 0; p < 2; p++)
                ldsm4(bf[2*p][0], bf[2*p][1], bf[2*p+1][0], bf[2*p+1][1], bAddr[p] + kOff);
            #pragma unroll
            for (int mt = 0; mt < 4; mt++)
                #pragma unroll
                for (int nt = 0; nt < 4; nt++)
                    mma_f16(acc[mt][nt], af[mt], bf[nt]);
        }

        if (++sc == N_STG) sc = 0;
    }

    // ---------------- epilogue ----------------
    float* Cf = (float*)Cv;
    __half* Ch = (__half*)Cv;
    #pragma unroll
    for (int mt = 0; mt < 4; mt++) {
        #pragma unroll
        for (int nt = 0; nt < 4; nt++) {
            const int r = row0 + wm + mt * 16 + g;
            const int c = col0 + wn + nt * 8 + 2 * t4;
            float v00 = acc[mt][nt][0], v01 = acc[mt][nt][1];
            float v10 = acc[mt][nt][2], v11 = acc[mt][nt][3];

            if (mode == EP_SILU_PAIR) {
                const int jn = N >> 1;
                const int j  = ((col0 + wn + nt * 8) >> 1) + t4;
                const float bb = bias[j];
                const float x0 = v00 + bb;
                const float x1 = v10 + bb;
                Ch[(size_t)r * jn + j]       = __float2half_rn(x0 / (1.f + __expf(-x0)) * v01);
                Ch[(size_t)(r + 8) * jn + j] = __float2half_rn(x1 / (1.f + __expf(-x1)) * v11);
            } else if (mode == EP_F16) {
                const size_t i0 = (size_t)r * N + c;
                const size_t i1 = i0 + (size_t)8 * N;
                *reinterpret_cast<uint32_t*>(&Ch[i0]) = f16x2(v00, v01);
                *reinterpret_cast<uint32_t*>(&Ch[i1]) = f16x2(v10, v11);
            } else {
                const size_t i0 = (size_t)r * N + c;
                const size_t i1 = i0 + (size_t)8 * N;
                if (mode == EP_RES) {
                    const float2 r0v = *reinterpret_cast<const float2*>(&res[i0]);
                    const float2 r1v = *reinterpret_cast<const float2*>(&res[i1]);
                    v00 += r0v.x; v01 += r0v.y; v10 += r1v.x; v11 += r1v.y;
                } else { // EP_BIAS_RES
                    const float2 bb  = *reinterpret_cast<const float2*>(&bias[c]);
                    const float2 r0v = *reinterpret_cast<const float2*>(&res[i0]);
                    const float2 r1v = *reinterpret_cast<const float2*>(&res[i1]);
                    v00 += bb.x + r0v.x; v01 += bb.y + r0v.y;
                    v10 += bb.x + r1v.x; v11 += bb.y + r1v.y;
                }
                *reinterpret_cast<float2*>(&Cf[i0]) = make_float2(v00, v01);
                *reinterpret_cast<float2*>(&Cf[i1]) = make_float2(v10, v11);
            }
        }
    }
}

// ---------------- FP16 flash attention (frozen R15 config) ----------------
#define AKS 72
#define KHALF_B (64 * AKS * 2)
#define KPAIR_B (128 * AKS * 2)
#define PTILE_B (128 * AKS * 2)
#define ATTN_SMEM_BYTES (2*KPAIR_B + 2*KPAIR_B + PTILE_B)   // 92160

__global__ __launch_bounds__(256, 2) void attn_mma(
    const __half* __restrict__ QKV, __half* __restrict__ O)
{
    extern __shared__ char smc[];
    const uint32_t sK = (uint32_t)__cvta_generic_to_shared(smc);
    const uint32_t sV = sK + 2 * KPAIR_B;
    const uint32_t sP = sV + 2 * KPAIR_B;
    __half* Ps = reinterpret_cast<__half*>(smc + 4 * KPAIR_B);

    const int tid  = threadIdx.x;
    const int lane = tid & 31;
    const int warp = tid >> 5;
    const int g    = lane >> 2;
    const int t4   = lane & 3;
    const int mi   = lane >> 3;
    const int ri   = lane & 7;

    const int qt = gridDim.x - 1 - blockIdx.x;
    const int bh = blockIdx.y;
    const int b  = bh >> 4, h = bh & 15;
    const size_t qoff = (size_t)b * LL * QS + (size_t)h * HDIM;
    const __half* qg  = QKV + qoff;
    const __half* kg0 = QKV + qoff + DD;
    const __half* vg0 = QKV + qoff + 2 * DD;

    const int qrow0 = qt * 128 + warp * 16;
    const int grow0 = qrow0 + g;
    const int grow1 = grow0 + 8;

    uint32_t qf[4][4];
    #pragma unroll
    for (int kd = 0; kd < 4; kd++) {
        const int c = kd * 16 + 2 * t4;
        qf[kd][0] = *reinterpret_cast<const uint32_t*>(&qg[(size_t)grow0 * QS + c]);
        qf[kd][1] = *reinterpret_cast<const uint32_t*>(&qg[(size_t)grow1 * QS + c]);
        qf[kd][2] = *reinterpret_cast<const uint32_t*>(&qg[(size_t)grow0 * QS + c + 8]);
        qf[kd][3] = *reinterpret_cast<const uint32_t*>(&qg[(size_t)grow1 * QS + c + 8]);
    }

    float oa[8][4];
    #pragma unroll
    for (int nt = 0; nt < 8; nt++)
        #pragma unroll
        for (int i = 0; i < 4; i++) oa[nt][i] = 0.f;
    float m0 = -1e30f, m1 = -1e30f, l0 = 0.f, l1 = 0.f;

    uint32_t kAddr[4];
    #pragma unroll
    for (int p = 0; p < 4; p++)
        kAddr[p] = sK + (uint32_t)((((2 * p + (mi >> 1)) * 8 + ri) * AKS * 2)
                                   + (mi & 1) * 16);
    uint32_t vAddr[4];
    #pragma unroll
    for (int p = 0; p < 4; p++)
        vAddr[p] = sV + (uint32_t)((((mi & 1) * 8 + ri) * AKS * 2)
                                   + (2 * p + (mi >> 1)) * 16);
    const uint32_t pAddr = sP + (uint32_t)(((warp * 16 + (mi & 1) * 8 + ri) * AKS * 2)
                                           + (mi >> 1) * 16);

    const int npair = qt + 1;

    {
        #pragma unroll
        for (int i = 0; i < 4; i++) {
            const int idx = tid + i * 256;
            const int r  = idx >> 3;
            const int c8 = (idx & 7) * 8;
            cp16(sK + (uint32_t)(r * AKS * 2 + (idx & 7) * 16), kg0 + (size_t)r * QS + c8);
            cp16(sV + (uint32_t)(r * AKS * 2 + (idx & 7) * 16), vg0 + (size_t)r * QS + c8);
        }
        asm volatile("cp.async.commit_group;");
    }

    for (int p2 = 0; p2 < npair; p2++) {
        const int cur = p2 & 1;
        asm volatile("cp.async.wait_group 0;");
        __syncthreads();

        if (p2 + 1 < npair) {
            const int nxt = cur ^ 1;
            const __half* kg = kg0 + (size_t)((p2 + 1) * 128) * QS;
            const __half* vg = vg0 + (size_t)((p2 + 1) * 128) * QS;
            const uint32_t bo = (uint32_t)(nxt * KPAIR_B);
            #pragma unroll
            for (int i = 0; i < 4; i++) {
                const int idx = tid + i * 256;
                const int r  = idx >> 3;
                const int c8 = (idx & 7) * 8;
                cp16(sK + bo + (uint32_t)(r * AKS * 2 + (idx & 7) * 16), kg + (size_t)r * QS + c8);
                cp16(sV + bo + (uint32_t)(r * AKS * 2 + (idx & 7) * 16), vg + (size_t)r * QS + c8);
            }
            asm volatile("cp.async.commit_group;");
        } else {
            asm volatile("cp.async.commit_group;");
        }

        #pragma unroll
        for (int hf = 0; hf < 2; hf++) {
            const int kt = 2 * p2 + hf;
            const uint32_t bufOff = (uint32_t)(cur * KPAIR_B) + (uint32_t)(hf * KHALF_B);

            float s[8][4];
            #pragma unroll
            for (int nt = 0; nt < 8; nt++)
                #pragma unroll
                for (int i = 0; i < 4; i++) s[nt][i] = 0.f;

            #pragma unroll
            for (int kd = 0; kd < 4; kd++) {
                uint32_t bf[8][2];
                #pragma unroll
                for (int p = 0; p < 4; p++)
                    ldsm4(bf[2*p][0], bf[2*p][1], bf[2*p+1][0], bf[2*p+1][1],
                          kAddr[p] + bufOff + (uint32_t)(kd * 32));
                #pragma unroll
                for (int nt = 0; nt < 8; nt++)
                    mma_f16(s[nt], qf[kd], bf[nt]);
            }

            const int key0 = kt * 64;
            const bool need_mask = (kt >= 2 * qt);
            #pragma unroll
            for (int nt = 0; nt < 8; nt++) {
                const int c0 = key0 + nt * 8 + 2 * t4;
                const int c1 = c0 + 1;
                s[nt][0] = s[nt][0] * 0.125f + 0.01f * (float)c0;
                s[nt][1] = s[nt][1] * 0.125f + 0.01f * (float)c1;
                s[nt][2] = s[nt][2] * 0.125f + 0.01f * (float)c0;
                s[nt][3] = s[nt][3] * 0.125f + 0.01f * (float)c1;
                if (need_mask) {
                    if (c0 > grow0) s[nt][0] = -1e30f;
                    if (c1 > grow0) s[nt][1] = -1e30f;
                    if (c0 > grow1) s[nt][2] = -1e30f;
                    if (c1 > grow1) s[nt][3] = -1e30f;
                }
            }

            float mx0 = -1e30f, mx1 = -1e30f;
            #pragma unroll
            for (int nt = 0; nt < 8; nt++) {
                mx0 = fmaxf(mx0, fmaxf(s[nt][0], s[nt][1]));
                mx1 = fmaxf(mx1, fmaxf(s[nt][2], s[nt][3]));
            }
            mx0 = fmaxf(mx0, __shfl_xor_sync(0xffffffffu, mx0, 1));
            mx0 = fmaxf(mx0, __shfl_xor_sync(0xffffffffu, mx0, 2));
            mx1 = fmaxf(mx1, __shfl_xor_sync(0xffffffffu, mx1, 1));
            mx1 = fmaxf(mx1, __shfl_xor_sync(0xffffffffu, mx1, 2));
            const float mn0 = fmaxf(m0, mx0);
            const float mn1 = fmaxf(m1, mx1);

            float sum0 = 0.f, sum1 = 0.f;
            #pragma unroll
            for (int nt = 0; nt < 8; nt++) {
                s[nt][0] = __expf(s[nt][0] - mn0);
                s[nt][1] = __expf(s[nt][1] - mn0);
                s[nt][2] = __expf(s[nt][2] - mn1);
                s[nt][3] = __expf(s[nt][3] - mn1);
                sum0 += s[nt][0] + s[nt][1];
                sum1 += s[nt][2] + s[nt][3];
            }
            sum0 += __shfl_xor_sync(0xffffffffu, sum0, 1);
            sum0 += __shfl_xor_sync(0xffffffffu, sum0, 2);
            sum1 += __shfl_xor_sync(0xffffffffu, sum1, 1);
            sum1 += __shfl_xor_sync(0xffffffffu, sum1, 2);

            const float corr0 = __expf(m0 - mn0);
            const float corr1 = __expf(m1 - mn1);
            l0 = l0 * corr0 + sum0;
            l1 = l1 * corr1 + sum1;
            m0 = mn0; m1 = mn1;
            #pragma unroll
            for (int nt = 0; nt < 8; nt++) {
                oa[nt][0] *= corr0; oa[nt][1] *= corr0;
                oa[nt][2] *= corr1; oa[nt][3] *= corr1;
            }

            {
                const int pr0 = warp * 16 + g;
                #pragma unroll
                for (int nt = 0; nt < 8; nt++) {
                    const int c = nt * 8 + 2 * t4;
                    *reinterpret_cast<uint32_t*>(&Ps[pr0 * AKS + c])       = f16x2(s[nt][0], s[nt][1]);
                    *reinterpret_cast<uint32_t*>(&Ps[(pr0 + 8) * AKS + c]) = f16x2(s[nt][2], s[nt][3]);
                }
            }
            __syncwarp();

            #pragma unroll
            for (int kd = 0; kd < 4; kd++) {
                uint32_t pa[4];
                ldsm4(pa[0], pa[1], pa[2], pa[3], pAddr + (uint32_t)(kd * 32));
                uint32_t vf[8][2];
                #pragma unroll
                for (int p = 0; p < 4; p++)
                    ldsm4t(vf[2*p][0], vf[2*p][1], vf[2*p+1][0], vf[2*p+1][1],
                           vAddr[p] + bufOff + (uint32_t)(kd * 16 * AKS * 2));
                #pragma unroll
                for (int nt = 0; nt < 8; nt++)
                    mma_f16(oa[nt], pa, vf[nt]);
            }
        }
    }

    const float inv0 = 1.f / l0;
    const float inv1 = 1.f / l1;
    __half* og = O + (size_t)b * LL * DD + (size_t)h * HDIM;
    #pragma unroll
    for (int nt = 0; nt < 8; nt++) {
        const int c = nt * 8 + 2 * t4;
        *reinterpret_cast<uint32_t*>(&og[(size_t)grow0 * DD + c]) =
            f16x2(oa[nt][0] * inv0, oa[nt][1] * inv0);
        *reinterpret_cast<uint32_t*>(&og[(size_t)grow1 * DD + c]) =
            f16x2(oa[nt][2] * inv1, oa[nt][3] * inv1);
    }
}

// ---------------- launch (graph-capture fork/join for weight prep) ----------------
static cudaStream_t g_side = nullptr;
static cudaEvent_t  g_evFork = nullptr, g_evJoin = nullptr;

extern "C" void kernel_launch(void* const* d_in, const int* in_sizes, int n_in,
                              void* d_out, int out_size)
{
    const float* x    = (const float*)d_in[0];
    const float* wq   = (const float*)d_in[2];
    const float* wk   = (const float*)d_in[3];
    const float* wv   = (const float*)d_in[4];
    const float* wo   = (const float*)d_in[5];
    const float* ln1g = (const float*)d_in[6];
    const float* ln1b = (const float*)d_in[7];
    const float* ln2g = (const float*)d_in[8];
    const float* ln2b = (const float*)d_in[9];
    const float* w1   = (const float*)d_in[10];
    const float* b1   = (const float*)d_in[11];
    const float* wg   = (const float*)d_in[12];
    const float* w2   = (const float*)d_in[13];
    const float* b2   = (const float*)d_in[14];
    float* out = (float*)d_out;

    __half *p_ln1, *p_qkv, *p_attn, *p_ln2, *p_f, *p_wh;
    float *p_h;
    cudaGetSymbolAddress((void**)&p_ln1,  g_ln1_h);
    cudaGetSymbolAddress((void**)&p_qkv,  g_qkv_h);
    cudaGetSymbolAddress((void**)&p_attn, g_attn_h);
    cudaGetSymbolAddress((void**)&p_h,    g_h);
    cudaGetSymbolAddress((void**)&p_ln2,  g_ln2_h);
    cudaGetSymbolAddress((void**)&p_f,    g_f_h);
    cudaGetSymbolAddress((void**)&p_wh,   g_wh);

    __half* rwqkv = p_wh;
    __half* rwo   = p_wh + (size_t)3*1024*1024;
    __half* rw1g  = p_wh + (size_t)4*1024*1024;
    __half* rw2   = p_wh + (size_t)12*1024*1024;

    cudaFuncSetAttribute(mma_gemm_f16, cudaFuncAttributeMaxDynamicSharedMemorySize,
                         GEMM_SMEM_BYTES);
    cudaFuncSetAttribute(attn_mma, cudaFuncAttributeMaxDynamicSharedMemorySize,
                         ATTN_SMEM_BYTES);

    if (g_side == nullptr) {
        cudaStreamCreateWithFlags(&g_side, cudaStreamNonBlocking);
        cudaEventCreateWithFlags(&g_evFork, cudaEventDisableTiming);
        cudaEventCreateWithFlags(&g_evJoin, cudaEventDisableTiming);
    }

    const int n4_d = DD*DD/4;
    const int n4_h = HIDD*DD/4;

    // ---- fork: side stream converts wo / w1g / w2 (needed only at steps 4/6/7) ----
    cudaEventRecord(g_evFork, 0);
    cudaStreamWaitEvent(g_side, g_evFork, 0);
    cvt_w  <<<(n4_d+255)/256, 256, 0, g_side>>>(wo, rwo, n4_d);
    cvt_ilv<<<(n4_h+255)/256, 256, 0, g_side>>>(w1, wg, rw1g);
    cvt_w  <<<(n4_h+255)/256, 256, 0, g_side>>>(w2, rw2, n4_h);
    cudaEventRecord(g_evJoin, g_side);

    // ---- main stream: qkv weight prep + ln1 + QKV GEMM + attention ----
    cvt_w3<<<(3*n4_d+255)/256, 256>>>(wq, wk, wv, rwqkv, n4_d);
    ln_kernel<<<NROWS, 256>>>(x, ln1g, ln1b, p_ln1);

    dim3 gQKV(QS / 128, NROWS / 128);
    mma_gemm_f16<<<gQKV, 256, GEMM_SMEM_BYTES>>>(p_ln1, rwqkv, p_qkv,
                                                 NROWS, QS, DD,
                                                 nullptr, nullptr, EP_F16);

    dim3 gAttn(LL / 128, BB * HH);
    attn_mma<<<gAttn, 256, ATTN_SMEM_BYTES>>>(p_qkv, p_attn);

    // ---- join: side-stream weight prep must be done before wo GEMM ----
    cudaStreamWaitEvent(0, g_evJoin, 0);

    dim3 gO(DD / 128, NROWS / 128);
    mma_gemm_f16<<<gO, 256, GEMM_SMEM_BYTES>>>(p_attn, rwo, p_h,
                                               NROWS, DD, DD,
                                               nullptr, x, EP_RES);

    ln_kernel<<<NROWS, 256>>>(p_h, ln2g, ln2b, p_ln2);

    dim3 gF(8192 / 128, NROWS / 128);
    mma_gemm_f16<<<gF, 256, GEMM_SMEM_BYTES>>>(p_ln2, rw1g, p_f,
                                               NROWS, 8192, DD,
                                               b1, nullptr, EP_SILU_PAIR);

    mma_gemm_f16<<<gO, 256, GEMM_SMEM_BYTES>>>(p_f, rw2, out,
                                               NROWS, DD, HIDD,
                                               b2, p_h, EP_BIAS_RES);
}

// round 17
// speedup vs baseline: 1.0205x; 1.0205x over previous
#include <cuda_runtime.h>
#include <cuda_fp16.h>
#include <math.h>
#include <stdint.h>

#define BB 2
#define LL 2048
#define DD 1024
#define HH 16
#define HDIM 64
#define HIDD 4096
#define NROWS (BB*LL)   // 4096
#define QS 3072         // packed qkv row stride

// ---------------- scratch (static device globals; no allocation) ----------------
__device__ __half g_ln1_h [NROWS*DD];
__device__ __half g_qkv_h [(size_t)NROWS*QS];
__device__ __half g_attn_h[NROWS*DD];
__device__ float  g_h     [NROWS*DD];
__device__ __half g_ln2_h [NROWS*DD];
__device__ __half g_f_h   [(size_t)NROWS*HIDD];
__device__ __half g_wh    [16*1024*1024];   // packed fp16 weights

// ---------------- PTX helpers ----------------
__device__ __forceinline__ void cp16(uint32_t saddr, const void* gaddr) {
    asm volatile("cp.async.cg.shared.global [%0], [%1], 16;" :: "r"(saddr), "l"(gaddr));
}
__device__ __forceinline__ uint32_t f16x2(float lo, float hi) {
    uint32_t r;
    asm("cvt.rn.f16x2.f32 %0, %1, %2;" : "=r"(r) : "f"(hi), "f"(lo));
    return r;
}
__device__ __forceinline__ void mma_f16(float c[4],
                                        const uint32_t a[4], const uint32_t b[2]) {
    asm volatile(
        "mma.sync.aligned.m16n8k16.row.col.f32.f16.f16.f32 "
        "{%0,%1,%2,%3}, {%4,%5,%6,%7}, {%8,%9}, {%0,%1,%2,%3};"
        : "+f"(c[0]), "+f"(c[1]), "+f"(c[2]), "+f"(c[3])
        : "r"(a[0]), "r"(a[1]), "r"(a[2]), "r"(a[3]), "r"(b[0]), "r"(b[1]));
}
__device__ __forceinline__ void ldsm4(uint32_t& r0, uint32_t& r1,
                                      uint32_t& r2, uint32_t& r3, uint32_t addr) {
    asm volatile("ldmatrix.sync.aligned.m8n8.x4.shared.b16 {%0,%1,%2,%3}, [%4];"
                 : "=r"(r0), "=r"(r1), "=r"(r2), "=r"(r3) : "r"(addr));
}
__device__ __forceinline__ void ldsm4t(uint32_t& r0, uint32_t& r1,
                                       uint32_t& r2, uint32_t& r3, uint32_t addr) {
    asm volatile("ldmatrix.sync.aligned.m8n8.x4.trans.shared.b16 {%0,%1,%2,%3}, [%4];"
                 : "=r"(r0), "=r"(r1), "=r"(r2), "=r"(r3) : "r"(addr));
}

// ---------------- weight prep ----------------
__global__ __launch_bounds__(256) void cvt_w3(const float* __restrict__ a,
                                              const float* __restrict__ b,
                                              const float* __restrict__ c,
                                              __half* __restrict__ outp, int n4)
{
    const int i = blockIdx.x * 256 + threadIdx.x;
    if (i < 3 * n4) {
        const int sel = i / n4;
        const int j   = i - sel * n4;
        const float* src = (sel == 0) ? a : (sel == 1) ? b : c;
        const float4 v = reinterpret_cast<const float4*>(src)[j];
        uint2 o;
        o.x = f16x2(v.x, v.y);
        o.y = f16x2(v.z, v.w);
        reinterpret_cast<uint2*>(outp)[i] = o;
    }
}
__global__ __launch_bounds__(256) void cvt_w(const float* __restrict__ in,
                                             __half* __restrict__ outp, int n4)
{
    const int i = blockIdx.x * 256 + threadIdx.x;
    if (i < n4) {
        const float4 v = reinterpret_cast<const float4*>(in)[i];
        uint2 o;
        o.x = f16x2(v.x, v.y);
        o.y = f16x2(v.z, v.w);
        reinterpret_cast<uint2*>(outp)[i] = o;
    }
}
__global__ __launch_bounds__(256) void cvt_ilv(const float* __restrict__ w1,
                                               const float* __restrict__ wg,
                                               __half* __restrict__ outp)
{
    const int t = blockIdx.x * 256 + threadIdx.x;
    if (t < HIDD * (DD/4)) {
        const int j  = t / (DD/4);
        const int k4 = t % (DD/4);
        const float4 a = reinterpret_cast<const float4*>(w1)[t];
        const float4 g = reinterpret_cast<const float4*>(wg)[t];
        uint2 oa, og;
        oa.x = f16x2(a.x, a.y); oa.y = f16x2(a.z, a.w);
        og.x = f16x2(g.x, g.y); og.y = f16x2(g.z, g.w);
        reinterpret_cast<uint2*>(outp)[(size_t)(2*j)     * (DD/4) + k4] = oa;
        reinterpret_cast<uint2*>(outp)[(size_t)(2*j + 1) * (DD/4) + k4] = og;
    }
}

// ---------------- LayerNorm: one warp per row, shuffle-only ----------------
__global__ __launch_bounds__(256) void ln_kernel(const float* __restrict__ x,
                                                 const float* __restrict__ gamma,
                                                 const float* __restrict__ beta,
                                                 __half* __restrict__ y)
{
    const int warp = threadIdx.x >> 5;
    const int lane = threadIdx.x & 31;
    const int row  = blockIdx.x * 8 + warp;

    const float4* xr = reinterpret_cast<const float4*>(x + (size_t)row * DD);
    float4 v[8];
    float s = 0.f, q = 0.f;
    #pragma unroll
    for (int i = 0; i < 8; i++) {
        v[i] = xr[lane + i * 32];
        s += v[i].x + v[i].y + v[i].z + v[i].w;
        q += v[i].x*v[i].x + v[i].y*v[i].y + v[i].z*v[i].z + v[i].w*v[i].w;
    }
    #pragma unroll
    for (int o = 16; o >= 1; o >>= 1) {
        s += __shfl_xor_sync(0xffffffffu, s, o);
        q += __shfl_xor_sync(0xffffffffu, q, o);
    }
    const float mu = s * (1.0f / DD);
    const float rs = rsqrtf(q * (1.0f / DD) - mu * mu + 1e-5f);

    const float4* gr = reinterpret_cast<const float4*>(gamma);
    const float4* br = reinterpret_cast<const float4*>(beta);
    uint2* yr = reinterpret_cast<uint2*>(y + (size_t)row * DD);
    #pragma unroll
    for (int i = 0; i < 8; i++) {
        const float4 g4 = gr[lane + i * 32];
        const float4 b4 = br[lane + i * 32];
        uint2 o;
        o.x = f16x2((v[i].x - mu) * rs * g4.x + b4.x, (v[i].y - mu) * rs * g4.y + b4.y);
        o.y = f16x2((v[i].z - mu) * rs * g4.z + b4.z, (v[i].w - mu) * rs * g4.w + b4.w);
        yr[lane + i * 32] = o;
    }
}

// ---------------- FP16 mma.sync GEMM (NT): 8 warps, 64x32 tiles (frozen) ----------------
#define EP_F16       0
#define EP_RES       1
#define EP_SILU_PAIR 2
#define EP_BIAS_RES  3

#define GBK   64
#define GROWB 144
#define STG_BYTES (128 * GROWB)
#define N_STG 3
#define GEMM_SMEM_BYTES (N_STG * 2 * STG_BYTES)   // 110592

__global__ __launch_bounds__(256, 2) void mma_gemm_f16(
    const __half* __restrict__ A, const __half* __restrict__ W,
    void* __restrict__ Cv, int M, int N, int K,
    const float* __restrict__ bias, const float* __restrict__ res, int mode)
{
    extern __shared__ char smc[];
    const uint32_t sBase = (uint32_t)__cvta_generic_to_shared(smc);
    const uint32_t sAbase = sBase;
    const uint32_t sBbase = sBase + N_STG * STG_BYTES;

    const int tid  = threadIdx.x;
    const int lane = tid & 31;
    const int warp = tid >> 5;
    const int g    = lane >> 2;
    const int t4   = lane & 3;
    const int wm   = (warp >> 2) * 64;
    const int wn   = (warp & 3)  * 32;
    const int row0 = blockIdx.y * 128;
    const int col0 = blockIdx.x * 128;

    const int lr  = tid >> 3;
    const int lc  = (tid & 7) * 8;

    const __half* Ag = A + (size_t)(row0 + lr) * K + lc;
    const __half* Wg = W + (size_t)(col0 + lr) * K + lc;
    const uint32_t sA = sAbase + (uint32_t)(lr * GROWB + (tid & 7) * 16);
    const uint32_t sB = sBbase + (uint32_t)(lr * GROWB + (tid & 7) * 16);
    const uint32_t rowB = (uint32_t)(32 * GROWB);

    const int mi = lane >> 3;
    const int ri = lane & 7;
    uint32_t aAddr[4], bAddr[2];
    #pragma unroll
    for (int mt = 0; mt < 4; mt++)
        aAddr[mt] = sAbase + (uint32_t)((wm + mt * 16 + (mi & 1) * 8 + ri) * GROWB
                                        + (mi >> 1) * 16);
    #pragma unroll
    for (int p = 0; p < 2; p++)
        bAddr[p] = sBbase + (uint32_t)((wn + (2 * p + (mi >> 1)) * 8 + ri) * GROWB
                                       + (mi & 1) * 16);

    float acc[4][4][4];
    #pragma unroll
    for (int mt = 0; mt < 4; mt++)
        #pragma unroll
        for (int nt = 0; nt < 4; nt++)
            #pragma unroll
            for (int i = 0; i < 4; i++) acc[mt][nt][i] = 0.f;

    const int nk = K / GBK;

    #pragma unroll
    for (int st = 0; st < 2; st++) {
        const int ko = st * GBK;
        const uint32_t so = (uint32_t)st * STG_BYTES;
        #pragma unroll
        for (int i = 0; i < 4; i++) {
            cp16(sA + so + (uint32_t)i * rowB, Ag + (size_t)(i * 32) * K + ko);
            cp16(sB + so + (uint32_t)i * rowB, Wg + (size_t)(i * 32) * K + ko);
        }
        asm volatile("cp.async.commit_group;");
    }

    int sc = 0;
    for (int kt = 0; kt < nk; kt++) {
        asm volatile("cp.async.wait_group 1;");
        __syncthreads();

        if (kt + 2 < nk) {
            const int ko = (kt + 2) * GBK;
            int sl = sc + 2; if (sl >= N_STG) sl -= N_STG;
            const uint32_t so = (uint32_t)sl * STG_BYTES;
            #pragma unroll
            for (int i = 0; i < 4; i++) {
                cp16(sA + so + (uint32_t)i * rowB, Ag + (size_t)(i * 32) * K + ko);
                cp16(sB + so + (uint32_t)i * rowB, Wg + (size_t)(i * 32) * K + ko);
            }
        }
        asm volatile("cp.async.commit_group;");

        const uint32_t stOff = (uint32_t)sc * STG_BYTES;
        #pragma unroll
        for (int ks = 0; ks < 4; ks++) {
            const uint32_t kOff = stOff + (uint32_t)(ks * 32);
            uint32_t af[4][4];
            uint32_t bf[4][2];
            #pragma unroll
            for (int mt = 0; mt < 4; mt++)
                ldsm4(af[mt][0], af[mt][1], af[mt][2], af[mt][3], aAddr[mt] + kOff);
            #pragma unroll
            for (int p = 0; p < 2; p++)
                ldsm4(bf[2*p][0], bf[2*p][1], bf[2*p+1][0], bf[2*p+1][1], bAddr[p] + kOff);
            #pragma unroll
            for (int mt = 0; mt < 4; mt++)
                #pragma unroll
                for (int nt = 0; nt < 4; nt++)
                    mma_f16(acc[mt][nt], af[mt], bf[nt]);
        }

        if (++sc == N_STG) sc = 0;
    }

    // ---------------- epilogue ----------------
    float* Cf = (float*)Cv;
    __half* Ch = (__half*)Cv;
    #pragma unroll
    for (int mt = 0; mt < 4; mt++) {
        #pragma unroll
        for (int nt = 0; nt < 4; nt++) {
            const int r = row0 + wm + mt * 16 + g;
            const int c = col0 + wn + nt * 8 + 2 * t4;
            float v00 = acc[mt][nt][0], v01 = acc[mt][nt][1];
            float v10 = acc[mt][nt][2], v11 = acc[mt][nt][3];

            if (mode == EP_SILU_PAIR) {
                const int jn = N >> 1;
                const int j  = ((col0 + wn + nt * 8) >> 1) + t4;
                const float bb = bias[j];
                const float x0 = v00 + bb;
                const float x1 = v10 + bb;
                Ch[(size_t)r * jn + j]       = __float2half_rn(x0 / (1.f + __expf(-x0)) * v01);
                Ch[(size_t)(r + 8) * jn + j] = __float2half_rn(x1 / (1.f + __expf(-x1)) * v11);
            } else if (mode == EP_F16) {
                const size_t i0 = (size_t)r * N + c;
                const size_t i1 = i0 + (size_t)8 * N;
                *reinterpret_cast<uint32_t*>(&Ch[i0]) = f16x2(v00, v01);
                *reinterpret_cast<uint32_t*>(&Ch[i1]) = f16x2(v10, v11);
            } else {
                const size_t i0 = (size_t)r * N + c;
                const size_t i1 = i0 + (size_t)8 * N;
                if (mode == EP_RES) {
                    const float2 r0v = *reinterpret_cast<const float2*>(&res[i0]);
                    const float2 r1v = *reinterpret_cast<const float2*>(&res[i1]);
                    v00 += r0v.x; v01 += r0v.y; v10 += r1v.x; v11 += r1v.y;
                } else { // EP_BIAS_RES
                    const float2 bb  = *reinterpret_cast<const float2*>(&bias[c]);
                    const float2 r0v = *reinterpret_cast<const float2*>(&res[i0]);
                    const float2 r1v = *reinterpret_cast<const float2*>(&res[i1]);
                    v00 += bb.x + r0v.x; v01 += bb.y + r0v.y;
                    v10 += bb.x + r1v.x; v11 += bb.y + r1v.y;
                }
                *reinterpret_cast<float2*>(&Cf[i0]) = make_float2(v00, v01);
                *reinterpret_cast<float2*>(&Cf[i1]) = make_float2(v10, v11);
            }
        }
    }
}

// ---------------- FP16 flash attention: fixed-shift softmax ----------------
// Shift m̂ = 0.01*row is a valid constant softmax shift (causality bounds
// bias-m̂ <= 0; |qk/8| <~ 1.6 => exp args <= ~1.6, no overflow; far keys
// underflow to 0 like true softmax weights ~e^-20).
#define AKS 72
#define KHALF_B (64 * AKS * 2)
#define KPAIR_B (128 * AKS * 2)
#define PTILE_B (128 * AKS * 2)
#define ATTN_SMEM_BYTES (2*KPAIR_B + 2*KPAIR_B + PTILE_B)   // 92160

__global__ __launch_bounds__(256, 2) void attn_mma(
    const __half* __restrict__ QKV, __half* __restrict__ O)
{
    extern __shared__ char smc[];
    const uint32_t sK = (uint32_t)__cvta_generic_to_shared(smc);
    const uint32_t sV = sK + 2 * KPAIR_B;
    const uint32_t sP = sV + 2 * KPAIR_B;
    __half* Ps = reinterpret_cast<__half*>(smc + 4 * KPAIR_B);

    const int tid  = threadIdx.x;
    const int lane = tid & 31;
    const int warp = tid >> 5;
    const int g    = lane >> 2;
    const int t4   = lane & 3;
    const int mi   = lane >> 3;
    const int ri   = lane & 7;

    const int qt = gridDim.x - 1 - blockIdx.x;   // longest-first
    const int bh = blockIdx.y;
    const int b  = bh >> 4, h = bh & 15;
    const size_t qoff = (size_t)b * LL * QS + (size_t)h * HDIM;
    const __half* qg  = QKV + qoff;
    const __half* kg0 = QKV + qoff + DD;
    const __half* vg0 = QKV + qoff + 2 * DD;

    const int qrow0 = qt * 128 + warp * 16;
    const int grow0 = qrow0 + g;
    const int grow1 = grow0 + 8;
    const float mh0 = 0.01f * (float)grow0;   // fixed softmax shift per row
    const float mh1 = 0.01f * (float)grow1;

    uint32_t qf[4][4];
    #pragma unroll
    for (int kd = 0; kd < 4; kd++) {
        const int c = kd * 16 + 2 * t4;
        qf[kd][0] = *reinterpret_cast<const uint32_t*>(&qg[(size_t)grow0 * QS + c]);
        qf[kd][1] = *reinterpret_cast<const uint32_t*>(&qg[(size_t)grow1 * QS + c]);
        qf[kd][2] = *reinterpret_cast<const uint32_t*>(&qg[(size_t)grow0 * QS + c + 8]);
        qf[kd][3] = *reinterpret_cast<const uint32_t*>(&qg[(size_t)grow1 * QS + c + 8]);
    }

    float oa[8][4];
    #pragma unroll
    for (int nt = 0; nt < 8; nt++)
        #pragma unroll
        for (int i = 0; i < 4; i++) oa[nt][i] = 0.f;
    float l0 = 0.f, l1 = 0.f;   // thread-local; reduced once at the end

    uint32_t kAddr[4];
    #pragma unroll
    for (int p = 0; p < 4; p++)
        kAddr[p] = sK + (uint32_t)((((2 * p + (mi >> 1)) * 8 + ri) * AKS * 2)
                                   + (mi & 1) * 16);
    uint32_t vAddr[4];
    #pragma unroll
    for (int p = 0; p < 4; p++)
        vAddr[p] = sV + (uint32_t)((((mi & 1) * 8 + ri) * AKS * 2)
                                   + (2 * p + (mi >> 1)) * 16);
    const uint32_t pAddr = sP + (uint32_t)(((warp * 16 + (mi & 1) * 8 + ri) * AKS * 2)
                                           + (mi >> 1) * 16);

    const int npair = qt + 1;

    {
        #pragma unroll
        for (int i = 0; i < 4; i++) {
            const int idx = tid + i * 256;
            const int r  = idx >> 3;
            const int c8 = (idx & 7) * 8;
            cp16(sK + (uint32_t)(r * AKS * 2 + (idx & 7) * 16), kg0 + (size_t)r * QS + c8);
            cp16(sV + (uint32_t)(r * AKS * 2 + (idx & 7) * 16), vg0 + (size_t)r * QS + c8);
        }
        asm volatile("cp.async.commit_group;");
    }

    for (int p2 = 0; p2 < npair; p2++) {
        const int cur = p2 & 1;
        asm volatile("cp.async.wait_group 0;");
        __syncthreads();

        if (p2 + 1 < npair) {
            const int nxt = cur ^ 1;
            const __half* kg = kg0 + (size_t)((p2 + 1) * 128) * QS;
            const __half* vg = vg0 + (size_t)((p2 + 1) * 128) * QS;
            const uint32_t bo = (uint32_t)(nxt * KPAIR_B);
            #pragma unroll
            for (int i = 0; i < 4; i++) {
                const int idx = tid + i * 256;
                const int r  = idx >> 3;
                const int c8 = (idx & 7) * 8;
                cp16(sK + bo + (uint32_t)(r * AKS * 2 + (idx & 7) * 16), kg + (size_t)r * QS + c8);
                cp16(sV + bo + (uint32_t)(r * AKS * 2 + (idx & 7) * 16), vg + (size_t)r * QS + c8);
            }
            asm volatile("cp.async.commit_group;");
        } else {
            asm volatile("cp.async.commit_group;");
        }

        #pragma unroll
        for (int hf = 0; hf < 2; hf++) {
            const int kt = 2 * p2 + hf;
            const uint32_t bufOff = (uint32_t)(cur * KPAIR_B) + (uint32_t)(hf * KHALF_B);

            float s[8][4];
            #pragma unroll
            for (int nt = 0; nt < 8; nt++)
                #pragma unroll
                for (int i = 0; i < 4; i++) s[nt][i] = 0.f;

            #pragma unroll
            for (int kd = 0; kd < 4; kd++) {
                uint32_t bf[8][2];
                #pragma unroll
                for (int p = 0; p < 4; p++)
                    ldsm4(bf[2*p][0], bf[2*p][1], bf[2*p+1][0], bf[2*p+1][1],
                          kAddr[p] + bufOff + (uint32_t)(kd * 32));
                #pragma unroll
                for (int nt = 0; nt < 8; nt++)
                    mma_f16(s[nt], qf[kd], bf[nt]);
            }

            // ---- scale + (bias - fixed shift) + mask + exp ----
            const int key0 = kt * 64;
            const bool need_mask = (kt >= 2 * qt);
            #pragma unroll
            for (int nt = 0; nt < 8; nt++) {
                const int c0 = key0 + nt * 8 + 2 * t4;
                const int c1 = c0 + 1;
                float a0 = s[nt][0] * 0.125f + (0.01f * (float)c0 - mh0);
                float a1 = s[nt][1] * 0.125f + (0.01f * (float)c1 - mh0);
                float a2 = s[nt][2] * 0.125f + (0.01f * (float)c0 - mh1);
                float a3 = s[nt][3] * 0.125f + (0.01f * (float)c1 - mh1);
                if (need_mask) {
                    if (c0 > grow0) a0 = -1e30f;
                    if (c1 > grow0) a1 = -1e30f;
                    if (c0 > grow1) a2 = -1e30f;
                    if (c1 > grow1) a3 = -1e30f;
                }
                s[nt][0] = __expf(a0);
                s[nt][1] = __expf(a1);
                s[nt][2] = __expf(a2);
                s[nt][3] = __expf(a3);
                l0 += s[nt][0] + s[nt][1];
                l1 += s[nt][2] + s[nt][3];
            }

            // ---- stage P (warp-private rows) ----
            {
                const int pr0 = warp * 16 + g;
                #pragma unroll
                for (int nt = 0; nt < 8; nt++) {
                    const int c = nt * 8 + 2 * t4;
                    *reinterpret_cast<uint32_t*>(&Ps[pr0 * AKS + c])       = f16x2(s[nt][0], s[nt][1]);
                    *reinterpret_cast<uint32_t*>(&Ps[(pr0 + 8) * AKS + c]) = f16x2(s[nt][2], s[nt][3]);
                }
            }
            __syncwarp();

            #pragma unroll
            for (int kd = 0; kd < 4; kd++) {
                uint32_t pa[4];
                ldsm4(pa[0], pa[1], pa[2], pa[3], pAddr + (uint32_t)(kd * 32));
                uint32_t vf[8][2];
                #pragma unroll
                for (int p = 0; p < 4; p++)
                    ldsm4t(vf[2*p][0], vf[2*p][1], vf[2*p+1][0], vf[2*p+1][1],
                           vAddr[p] + bufOff + (uint32_t)(kd * 16 * AKS * 2));
                #pragma unroll
                for (int nt = 0; nt < 8; nt++)
                    mma_f16(oa[nt], pa, vf[nt]);
            }
        }
    }

    // final l reduction across the t4 quad (rows live in lanes with same g)
    l0 += __shfl_xor_sync(0xffffffffu, l0, 1);
    l0 += __shfl_xor_sync(0xffffffffu, l0, 2);
    l1 += __shfl_xor_sync(0xffffffffu, l1, 1);
    l1 += __shfl_xor_sync(0xffffffffu, l1, 2);

    const float inv0 = 1.f / l0;
    const float inv1 = 1.f / l1;
    __half* og = O + (size_t)b * LL * DD + (size_t)h * HDIM;
    #pragma unroll
    for (int nt = 0; nt < 8; nt++) {
        const int c = nt * 8 + 2 * t4;
        *reinterpret_cast<uint32_t*>(&og[(size_t)grow0 * DD + c]) =
            f16x2(oa[nt][0] * inv0, oa[nt][1] * inv0);
        *reinterpret_cast<uint32_t*>(&og[(size_t)grow1 * DD + c]) =
            f16x2(oa[nt][2] * inv1, oa[nt][3] * inv1);
    }
}

// ---------------- launch (graph-capture fork/join for weight prep) ----------------
static cudaStream_t g_side = nullptr;
static cudaEvent_t  g_evFork = nullptr, g_evJoin = nullptr;

extern "C" void kernel_launch(void* const* d_in, const int* in_sizes, int n_in,
                              void* d_out, int out_size)
{
    const float* x    = (const float*)d_in[0];
    const float* wq   = (const float*)d_in[2];
    const float* wk   = (const float*)d_in[3];
    const float* wv   = (const float*)d_in[4];
    const float* wo   = (const float*)d_in[5];
    const float* ln1g = (const float*)d_in[6];
    const float* ln1b = (const float*)d_in[7];
    const float* ln2g = (const float*)d_in[8];
    const float* ln2b = (const float*)d_in[9];
    const float* w1   = (const float*)d_in[10];
    const float* b1   = (const float*)d_in[11];
    const float* wg   = (const float*)d_in[12];
    const float* w2   = (const float*)d_in[13];
    const float* b2   = (const float*)d_in[14];
    float* out = (float*)d_out;

    __half *p_ln1, *p_qkv, *p_attn, *p_ln2, *p_f, *p_wh;
    float *p_h;
    cudaGetSymbolAddress((void**)&p_ln1,  g_ln1_h);
    cudaGetSymbolAddress((void**)&p_qkv,  g_qkv_h);
    cudaGetSymbolAddress((void**)&p_attn, g_attn_h);
    cudaGetSymbolAddress((void**)&p_h,    g_h);
    cudaGetSymbolAddress((void**)&p_ln2,  g_ln2_h);
    cudaGetSymbolAddress((void**)&p_f,    g_f_h);
    cudaGetSymbolAddress((void**)&p_wh,   g_wh);

    __half* rwqkv = p_wh;
    __half* rwo   = p_wh + (size_t)3*1024*1024;
    __half* rw1g  = p_wh + (size_t)4*1024*1024;
    __half* rw2   = p_wh + (size_t)12*1024*1024;

    cudaFuncSetAttribute(mma_gemm_f16, cudaFuncAttributeMaxDynamicSharedMemorySize,
                         GEMM_SMEM_BYTES);
    cudaFuncSetAttribute(attn_mma, cudaFuncAttributeMaxDynamicSharedMemorySize,
                         ATTN_SMEM_BYTES);

    if (g_side == nullptr) {
        cudaStreamCreateWithFlags(&g_side, cudaStreamNonBlocking);
        cudaEventCreateWithFlags(&g_evFork, cudaEventDisableTiming);
        cudaEventCreateWithFlags(&g_evJoin, cudaEventDisableTiming);
    }

    const int n4_d = DD*DD/4;
    const int n4_h = HIDD*DD/4;

    // ---- fork: side stream converts wo / w1g / w2 ----
    cudaEventRecord(g_evFork, 0);
    cudaStreamWaitEvent(g_side, g_evFork, 0);
    cvt_w  <<<(n4_d+255)/256, 256, 0, g_side>>>(wo, rwo, n4_d);
    cvt_ilv<<<(n4_h+255)/256, 256, 0, g_side>>>(w1, wg, rw1g);
    cvt_w  <<<(n4_h+255)/256, 256, 0, g_side>>>(w2, rw2, n4_h);
    cudaEventRecord(g_evJoin, g_side);

    // ---- main stream ----
    cvt_w3<<<(3*n4_d+255)/256, 256>>>(wq, wk, wv, rwqkv, n4_d);
    ln_kernel<<<NROWS/8, 256>>>(x, ln1g, ln1b, p_ln1);

    dim3 gQKV(QS / 128, NROWS / 128);
    mma_gemm_f16<<<gQKV, 256, GEMM_SMEM_BYTES>>>(p_ln1, rwqkv, p_qkv,
                                                 NROWS, QS, DD,
                                                 nullptr, nullptr, EP_F16);

    dim3 gAttn(LL / 128, BB * HH);
    attn_mma<<<gAttn, 256, ATTN_SMEM_BYTES>>>(p_qkv, p_attn);

    cudaStreamWaitEvent(0, g_evJoin, 0);

    dim3 gO(DD / 128, NROWS / 128);
    mma_gemm_f16<<<gO, 256, GEMM_SMEM_BYTES>>>(p_attn, rwo, p_h,
                                               NROWS, DD, DD,
                                               nullptr, x, EP_RES);

    ln_kernel<<<NROWS/8, 256>>>(p_h, ln2g, ln2b, p_ln2);

    dim3 gF(8192 / 128, NROWS / 128);
    mma_gemm_f16<<<gF, 256, GEMM_SMEM_BYTES>>>(p_ln2, rw1g, p_f,
                                               NROWS, 8192, DD,
                                               b1, nullptr, EP_SILU_PAIR);

    mma_gemm_f16<<<gO, 256, GEMM_SMEM_BYTES>>>(p_f, rw2, out,
                                               NROWS, DD, HIDD,
                                               b2, p_h, EP_BIAS_RES);
}